// round 12
// baseline (speedup 1.0000x reference)
#include <cuda_runtime.h>
#include <math.h>

#define NB 8
#define NT 512
#define NH 256
#define NM 4096
#define NW 256

typedef unsigned long long ull;

#define FMA2(d,a,b,c) asm("fma.rn.f32x2 %0,%1,%2,%3;" : "=l"(d) : "l"(a), "l"(b), "l"(c))
#define MUL2(d,a,b)   asm("mul.rn.f32x2 %0,%1,%2;"    : "=l"(d) : "l"(a), "l"(b))
#define ADD2(d,a,b)   asm("add.rn.f32x2 %0,%1,%2;"    : "=l"(d) : "l"(a), "l"(b))

__device__ __forceinline__ ull pk2(float a, float b) {
    ull d;
    asm("mov.b64 %0,{%1,%2};" : "=l"(d) : "r"(__float_as_uint(a)), "r"(__float_as_uint(b)));
    return d;
}
__device__ __forceinline__ void unpk2(ull v, float& a, float& b) {
    unsigned int l, h;
    asm("mov.b64 {%0,%1},%2;" : "=r"(l), "=r"(h) : "l"(v));
    a = __uint_as_float(l); b = __uint_as_float(h);
}

// ---------------- scratch ----------------
__device__ float g_h1[NB*NT*NH];
__device__ float g_h2[NB*NT*NH];
__device__ float g_m0[NB*NT];
__device__ float g_center[NB*NT];
__device__ int   g_phs[NB*NW];
__device__ int   g_phc[NB*NW];
__device__ int   g_mels[NB*NW];
__device__ int   g_melc[NB*NW];
__device__ int   g_cmel[NB*NW];
__device__ float g_w1T[NH*5*NH + 5*NH];   // [(i*5+k)*NH + o], +1 row pad for prefetch
__device__ float g_w2T[NH*5*NH + 5*NH];
__device__ float g_pwT[NH*NH];            // [i*NH + o]

// ---------------- weight transpose + cmel zero ----------------
__global__ void transpose_weights(const float* __restrict__ w1,
                                  const float* __restrict__ w2,
                                  const float* __restrict__ pw)
{
    int o = threadIdx.x;
    int j = blockIdx.x;
    if (j < 1280) {
        g_w1T[j * NH + o] = w1[(size_t)o * 1280 + j];
    } else if (j < 2560) {
        int jj = j - 1280;
        g_w2T[jj * NH + o] = w2[(size_t)o * 1280 + jj];
    } else if (j < 2816) {
        int jj = j - 2560;
        g_pwT[jj * NH + o] = pw[(size_t)o * NH + jj];
    } else {
        int b = j - 2816;
        g_cmel[b * NW + o] = 0;
    }
}

// ---------------- parallel mel histogram ----------------
__global__ void mel_hist(const int* __restrict__ mel2w)
{
    int b = blockIdx.y;
    int t = blockIdx.x * 256 + threadIdx.x;
    int w = mel2w[(size_t)b * NM + t] - 1;
    atomicAdd(&g_cmel[b * NW + w], 1);
}

// ---------------- conv5 + channel-LN + relu ----------------
// 512-thread block = two 256-thread groups, each running the R9 TT=16 per-thread
// program (pairs (t, t+8), weight prefetch) on its own staging region.
// Both groups read identical weight addresses -> one shared L1 weight stream.
__global__ void __launch_bounds__(512, 1) conv_ln_relu(
                             const float* __restrict__ in,
                             const float* __restrict__ mask,
                             const float* __restrict__ wT,    // [(i*5+k)*NH + o], padded
                             const float* __restrict__ bias,
                             const float* __restrict__ lng,
                             const float* __restrict__ lnb,
                             float* __restrict__ out)
{
    const int TT = 16;
    __shared__ ull spu[2][12 * NH];           // 48 KB; per-group pair rows
    __shared__ float mu_s[2][TT], rs_s[2][TT];

    int tid = threadIdx.x;
    int g   = tid >> 8;                       // group 0/1
    int o   = tid & 255;

    int b   = blockIdx.x / (NT / 32);
    int t0  = (blockIdx.x % (NT / 32)) * 32;
    int tg0 = t0 + g * TT;                    // this group's tile start

    ull* spg = spu[g];
    float* spf = (float*)spg;
    for (int idx = o; idx < 20 * NH; idx += 256) {
        int v = idx >> 8; int i = idx & 255;    // v -> x[tg0+v-2]
        int t = tg0 + v - 2;
        float val = 0.0f;
        if (t >= 0 && t < NT) val = in[((size_t)b * NT + t) * NH + i] * mask[b * NT + t];
        if (v < 12)  spf[(v * NH + i) * 2]           = val;
        if (v >= 8)  spf[((v - 8) * NH + i) * 2 + 1] = val;
    }
    __syncthreads();

    ull acc2[8];
    {
        float bo = bias[o];
        ull bp = pk2(bo, bo);
        #pragma unroll
        for (int j = 0; j < 8; j++) acc2[j] = bp;
    }

    // software-pipelined weight loads (prefetch i+1; pad row keeps last load in-bounds)
    const float* wp = wT + o;
    float c0 = wp[0], c1 = wp[NH], c2 = wp[2*NH], c3 = wp[3*NH], c4 = wp[4*NH];
    #pragma unroll 2
    for (int i = 0; i < NH; i++) {
        wp += 5 * NH;
        float n0 = wp[0], n1 = wp[NH], n2 = wp[2*NH], n3 = wp[3*NH], n4 = wp[4*NH];
        ull W0 = pk2(c0, c0), W1 = pk2(c1, c1), W2 = pk2(c2, c2), W3 = pk2(c3, c3), W4 = pk2(c4, c4);
        ull p0 = spg[i], p1 = spg[NH + i], p2 = spg[2 * NH + i], p3 = spg[3 * NH + i];
        #pragma unroll
        for (int j = 0; j < 8; j++) {
            ull p4 = spg[(j + 4) * NH + i];
            ull s;
            MUL2(s, p0, W0);
            FMA2(s, p1, W1, s);
            FMA2(s, p2, W2, s);
            FMA2(s, p3, W3, s);
            FMA2(s, p4, W4, s);
            ADD2(acc2[j], acc2[j], s);
            p0 = p1; p1 = p2; p2 = p3; p3 = p4;
        }
        c0 = n0; c1 = n1; c2 = n2; c3 = n3; c4 = n4;
    }
    __syncthreads();

    float* ys = (float*)spg;                  // reuse own region: ys[t*NH + c]
    #pragma unroll
    for (int j = 0; j < 8; j++) {
        float a, bb;
        unpk2(acc2[j], a, bb);
        ys[j * NH + o]       = a;             // t = j
        ys[(j + 8) * NH + o] = bb;            // t = j + 8
    }
    __syncthreads();

    int w16 = tid >> 5;                       // 0..15
    int wl  = w16 & 7;                        // warp within group
    int lane = tid & 31;
    for (int t = wl; t < TT; t += 8) {
        float s = 0.0f;
        for (int c = lane; c < NH; c += 32) s += ys[t * NH + c];
        for (int off = 16; off; off >>= 1) s += __shfl_xor_sync(0xffffffffu, s, off);
        float mu = s * (1.0f / NH);
        float v = 0.0f;
        for (int c = lane; c < NH; c += 32) { float d = ys[t * NH + c] - mu; v = fmaf(d, d, v); }
        for (int off = 16; off; off >>= 1) v += __shfl_xor_sync(0xffffffffu, v, off);
        v *= (1.0f / NH);
        if (lane == 0) { mu_s[g][t] = mu; rs_s[g][t] = 1.0f / sqrtf(v + 1e-4f); }
    }
    __syncthreads();

    float go = lng[o], b2 = lnb[o];
    #pragma unroll
    for (int t = 0; t < TT; t++) {
        float y = (ys[t * NH + o] - mu_s[g][t]) * rs_s[g][t] * go + b2;
        out[((size_t)b * NT + tg0 + t) * NH + o] = fmaxf(y, 0.0f);
    }
}

// ---------------- proj 1x1 + residual + gauss ch0 -> m0 (TT=16, best-known) ----------------
__global__ void __launch_bounds__(256) proj_gauss(
                           const float* __restrict__ x,
                           const float* __restrict__ mask,
                           const float* __restrict__ pb,
                           const float* __restrict__ gw,
                           const float* __restrict__ gb)
{
    const int TT = 16;
    __shared__ float hs[TT][NH];
    __shared__ float red2[256][TT + 1];

    int b  = blockIdx.x / (NT / TT);
    int t0 = (blockIdx.x % (NT / TT)) * TT;
    int o  = threadIdx.x;

    for (int idx = o; idx < TT * NH; idx += 256) {
        int tt = idx >> 8; int i = idx & 255;
        hs[tt][i] = g_h2[((size_t)b * NT + t0 + tt) * NH + i];
    }
    __syncthreads();

    float acc[TT];
    float pbo = pb[o];
    #pragma unroll
    for (int t = 0; t < TT; t++) acc[t] = pbo;

    const float* pwp = g_pwT + o;
    for (int i = 0; i < NH; i++) {
        float w = pwp[i * NH];
        #pragma unroll
        for (int t = 0; t < TT; t++) acc[t] = fmaf(w, hs[t][i], acc[t]);
    }

    float gwo = gw[o];
    #pragma unroll
    for (int t = 0; t < TT; t++) {
        float mt = mask[b * NT + t0 + t];
        float v = (x[((size_t)b * NT + t0 + t) * NH + o] + acc[t]) * mt;
        red2[o][t] = gwo * v;
    }
    __syncthreads();

    #pragma unroll
    for (int s = 128; s > 0; s >>= 1) {
        if (o < s) {
            #pragma unroll
            for (int t = 0; t < TT; t++) red2[o][t] += red2[o + s][t];
        }
        __syncthreads();
    }
    if (o < TT) {
        float g0 = red2[0][o] + gb[0];
        float mt = mask[b * NT + t0 + o];
        g_m0[b * NT + t0 + o] = (fmaxf(g0, 0.0f) + 1.0f) * mt;
    }
}

// ---------------- word stats, rescale, cumsum -> center ----------------
__global__ void stats_kernel(const int* __restrict__ x2w,
                             float* __restrict__ mword_out)
{
    int b = blockIdx.x;
    int tid = threadIdx.x;
    __shared__ int   cph[NW], sph[NW], smel[NW];
    __shared__ float sc[NW];
    __shared__ float mbuf[NT];

    if (tid < NW) cph[tid] = 0;
    __syncthreads();
    for (int p = tid; p < NT; p += 256) atomicAdd(&cph[x2w[b * NT + p] - 1], 1);
    __syncthreads();
    if (tid == 0) { int s = 0; for (int w = 0; w < NW; w++) { sph[w]  = s; s += cph[w]; } }
    if (tid == 1) { int s = 0; for (int w = 0; w < NW; w++) { smel[w] = s; s += g_cmel[b * NW + w]; } }
    __syncthreads();

    if (tid < NW) {
        int w = tid;
        int st = sph[w], c = cph[w];
        int cm = g_cmel[b * NW + w];
        float s = 0.0f;
        for (int j = 0; j < c; j++) s += g_m0[b * NT + st + j];
        mword_out[b * NW + w] = s;
        sc[w] = (float)cm / (s + 1e-4f);
        g_phs[b * NW + w] = st;      g_phc[b * NW + w] = c;
        g_mels[b * NW + w] = smel[w]; g_melc[b * NW + w] = cm;
    }
    __syncthreads();

    for (int p = tid; p < NT; p += 256) {
        int w = x2w[b * NT + p] - 1;
        float m0 = g_m0[b * NT + p];
        float d  = __fmul_rn(sc[w] - 1.0f, m0);
        mbuf[p]  = __fadd_rn(m0, d);
    }
    __syncthreads();

    if (tid == 0) {
        float c = 0.0f;
        for (int p = 0; p < NT; p++) {
            c = __fadd_rn(c, mbuf[p]);
            float half = __fmul_rn(0.5f, mbuf[p]);
            g_center[b * NT + p] = __fadd_rn(c, -half);
        }
    }
}

// ---------------- fused attention: missing-word blocks FIRST, then matched rows ----------------
#define MISS_BLKS (NW * NB * 4)     // 8192
__global__ void __launch_bounds__(256) attn_fused(
                             const float* __restrict__ x,
                             const int* __restrict__ mel2w,
                             float* __restrict__ outA,
                             float* __restrict__ outW)
{
    __shared__ float wsm[8][64];
    __shared__ float wts[8][NT];
    __shared__ float cen[NT];
    __shared__ float redA[8], redB[8];

    if (blockIdx.x < MISS_BLKS) {
        int idx = blockIdx.x;
        int w = idx & 255;
        int b = (idx >> 8) & 7;
        int z = idx >> 11;               // 0..3
        if (g_phc[b * NW + w] != 0) return;
        int mc = g_melc[b * NW + w];
        if (mc == 0) return;
        int ms = g_mels[b * NW + w];

        int tid = threadIdx.x;
        int lane = tid & 31, warp = tid >> 5;

        for (int p = tid; p < NT; p += 256) cen[p] = g_center[b * NT + p];
        __syncthreads();

        for (int r0 = z * 8; r0 < mc; r0 += 32) {
            int RT = min(8, mc - r0);
            for (int r = 0; r < RT; r++) {
                float tp = (float)(ms + r0 + r);
                float d0 = cen[tid] - tp;
                float lg0 = -(__fmul_rn(d0, d0)) / 10.0f;
                float m0v = __fadd_rn(lg0, -1e9f);
                float d1 = cen[tid + 256] - tp;
                float lg1 = -(__fmul_rn(d1, d1)) / 10.0f;
                float m1v = __fadd_rn(lg1, -1e9f);

                float mx = fmaxf(m0v, m1v);
                for (int off = 16; off; off >>= 1) mx = fmaxf(mx, __shfl_xor_sync(0xffffffffu, mx, off));
                if (lane == 0) redA[warp] = mx;
                __syncthreads();
                float mall = redA[0];
                #pragma unroll
                for (int k = 1; k < 8; k++) mall = fmaxf(mall, redA[k]);

                float e0 = expf(m0v - mall);
                float e1 = expf(m1v - mall);
                float ss = e0 + e1;
                for (int off = 16; off; off >>= 1) ss += __shfl_xor_sync(0xffffffffu, ss, off);
                if (lane == 0) redB[warp] = ss;
                __syncthreads();
                float tot = redB[0];
                #pragma unroll
                for (int k = 1; k < 8; k++) tot += redB[k];

                float w0 = e0 / tot, w1 = e1 / tot;
                wts[r][tid] = w0; wts[r][tid + 256] = w1;
                size_t wb = ((size_t)b * NM + ms + r0 + r) * NT;
                outW[wb + tid] = w0; outW[wb + tid + 256] = w1;
                __syncthreads();
            }
            __syncthreads();

            float a[8];
            #pragma unroll
            for (int r = 0; r < 8; r++) a[r] = 0.0f;
            for (int p = 0; p < NT; p++) {
                float xv = x[((size_t)b * NT + p) * NH + tid];
                #pragma unroll
                for (int r = 0; r < 8; r++) a[r] = fmaf(wts[r][p], xv, a[r]);
            }
            for (int r = 0; r < RT; r++)
                outA[((size_t)b * NM + ms + r0 + r) * NH + tid] = a[r];
            __syncthreads();
        }
    } else {
        int warp = threadIdx.x >> 5, lane = threadIdx.x & 31;
        int row = (blockIdx.x - MISS_BLKS) * 8 + warp;
        int b = row >> 12;
        int t = row & 4095;

        int w = mel2w[(size_t)b * NM + t] - 1;
        int cnt = g_phc[b * NW + w];
        if (cnt == 0) return;
        int lo = g_phs[b * NW + w];
        float tp = (float)t;

        float l0 = -3.4e38f, l1 = -3.4e38f;
        if (lane < cnt) {
            float d = g_center[b * NT + lo + lane] - tp;
            l0 = -(__fmul_rn(d, d)) / 10.0f;
        }
        if (lane + 32 < cnt) {
            float d = g_center[b * NT + lo + lane + 32] - tp;
            l1 = -(__fmul_rn(d, d)) / 10.0f;
        }
        float mx = fmaxf(l0, l1);
        for (int off = 16; off; off >>= 1) mx = fmaxf(mx, __shfl_xor_sync(0xffffffffu, mx, off));
        float e0 = (lane < cnt)      ? expf(l0 - mx) : 0.0f;
        float e1 = (lane + 32 < cnt) ? expf(l1 - mx) : 0.0f;
        float s = e0 + e1;
        for (int off = 16; off; off >>= 1) s += __shfl_xor_sync(0xffffffffu, s, off);
        wsm[warp][lane]      = e0 / s;
        wsm[warp][lane + 32] = e1 / s;
        __syncwarp();

        size_t wbase = ((size_t)b * NM + t) * NT;
        float4* w4 = (float4*)(outW + wbase);
        #pragma unroll
        for (int q = 0; q < 4; q++) {
            int p = q * 128 + lane * 4;
            int j0 = p - lo;
            float4 v;
            v.x = ((unsigned)(j0)     < (unsigned)cnt) ? wsm[warp][j0]     : 0.0f;
            v.y = ((unsigned)(j0 + 1) < (unsigned)cnt) ? wsm[warp][j0 + 1] : 0.0f;
            v.z = ((unsigned)(j0 + 2) < (unsigned)cnt) ? wsm[warp][j0 + 2] : 0.0f;
            v.w = ((unsigned)(j0 + 3) < (unsigned)cnt) ? wsm[warp][j0 + 3] : 0.0f;
            w4[q * 32 + lane] = v;
        }

        float4 a0 = make_float4(0.f, 0.f, 0.f, 0.f);
        float4 a1 = make_float4(0.f, 0.f, 0.f, 0.f);
        for (int j = 0; j < cnt; j++) {
            float wj = wsm[warp][j];
            const float4* xr = (const float4*)(x + ((size_t)b * NT + lo + j) * NH);
            float4 v0 = xr[lane * 2], v1 = xr[lane * 2 + 1];
            a0.x = fmaf(wj, v0.x, a0.x); a0.y = fmaf(wj, v0.y, a0.y);
            a0.z = fmaf(wj, v0.z, a0.z); a0.w = fmaf(wj, v0.w, a0.w);
            a1.x = fmaf(wj, v1.x, a1.x); a1.y = fmaf(wj, v1.y, a1.y);
            a1.z = fmaf(wj, v1.z, a1.z); a1.w = fmaf(wj, v1.w, a1.w);
        }
        float4* o4 = (float4*)(outA + ((size_t)b * NM + t) * NH);
        o4[lane * 2]     = a0;
        o4[lane * 2 + 1] = a1;
    }
}

// ---------------- launcher ----------------
extern "C" void kernel_launch(void* const* d_in, const int* in_sizes, int n_in,
                              void* d_out, int out_size)
{
    const float* x       = (const float*)d_in[0];
    const float* x_mask  = (const float*)d_in[1];
    const float* pre_w1  = (const float*)d_in[2];
    const float* pre_b1  = (const float*)d_in[3];
    const float* ln1_g   = (const float*)d_in[4];
    const float* ln1_b   = (const float*)d_in[5];
    const float* pre_w2  = (const float*)d_in[6];
    const float* pre_b2  = (const float*)d_in[7];
    const float* ln2_g   = (const float*)d_in[8];
    const float* ln2_b   = (const float*)d_in[9];
    const float* proj_w  = (const float*)d_in[10];
    const float* proj_b  = (const float*)d_in[11];
    const float* gauss_w = (const float*)d_in[12];
    const float* gauss_b = (const float*)d_in[13];
    const int*   x2word  = (const int*)d_in[14];
    const int*   mel2word= (const int*)d_in[15];

    float* outA  = (float*)d_out;
    float* outW  = outA + (size_t)NB * NM * NH;
    float* outMW = outW + (size_t)NB * NM * NT;

    float* h1;  cudaGetSymbolAddress((void**)&h1,  g_h1);
    float* h2;  cudaGetSymbolAddress((void**)&h2,  g_h2);
    float* w1T; cudaGetSymbolAddress((void**)&w1T, g_w1T);
    float* w2T; cudaGetSymbolAddress((void**)&w2T, g_w2T);

    transpose_weights<<<2824, 256>>>(pre_w1, pre_w2, proj_w);
    mel_hist<<<dim3(NM / 256, NB), 256>>>(mel2word);
    conv_ln_relu<<<NB * (NT / 32), 512>>>(x,  x_mask, w1T, pre_b1, ln1_g, ln1_b, h1);
    conv_ln_relu<<<NB * (NT / 32), 512>>>(h1, x_mask, w2T, pre_b2, ln2_g, ln2_b, h2);
    proj_gauss  <<<NB * (NT / 16), 256>>>(x, x_mask, proj_b, gauss_w, gauss_b);
    stats_kernel<<<NB, 256>>>(x2word, outMW);
    attn_fused  <<<MISS_BLKS + NB * NM / 8, 256>>>(x, mel2word, outA, outW);
}

// round 14
// speedup vs baseline: 1.0219x; 1.0219x over previous
#include <cuda_runtime.h>
#include <math.h>

#define NB 8
#define NT 512
#define NH 256
#define NM 4096
#define NW 256

typedef unsigned long long ull;

#define FMA2(d,a,b,c) asm("fma.rn.f32x2 %0,%1,%2,%3;" : "=l"(d) : "l"(a), "l"(b), "l"(c))
#define MUL2(d,a,b)   asm("mul.rn.f32x2 %0,%1,%2;"    : "=l"(d) : "l"(a), "l"(b))
#define ADD2(d,a,b)   asm("add.rn.f32x2 %0,%1,%2;"    : "=l"(d) : "l"(a), "l"(b))

__device__ __forceinline__ ull pk2(float a, float b) {
    ull d;
    asm("mov.b64 %0,{%1,%2};" : "=l"(d) : "r"(__float_as_uint(a)), "r"(__float_as_uint(b)));
    return d;
}
__device__ __forceinline__ void unpk2(ull v, float& a, float& b) {
    unsigned int l, h;
    asm("mov.b64 {%0,%1},%2;" : "=r"(l), "=r"(h) : "l"(v));
    a = __uint_as_float(l); b = __uint_as_float(h);
}

// ---------------- scratch ----------------
__device__ float g_h1[NB*NT*NH];
__device__ float g_h2[NB*NT*NH];
__device__ float g_m0[NB*NT];
__device__ float g_center[NB*NT];
__device__ int   g_phs[NB*NW];
__device__ int   g_phc[NB*NW];
__device__ int   g_mels[NB*NW];
__device__ int   g_melc[NB*NW];
__device__ int   g_cmel[NB*NW];
__device__ float g_w1T[NH*5*NH + 10*NH];  // [(i*5+k)*NH + o], +2 i-row pad for 2-deep prefetch
__device__ float g_w2T[NH*5*NH + 10*NH];
__device__ float g_pwT[NH*NH];            // [i*NH + o]

// ---------------- weight transpose + cmel zero ----------------
__global__ void transpose_weights(const float* __restrict__ w1,
                                  const float* __restrict__ w2,
                                  const float* __restrict__ pw)
{
    int o = threadIdx.x;
    int j = blockIdx.x;
    if (j < 1280) {
        g_w1T[j * NH + o] = w1[(size_t)o * 1280 + j];
    } else if (j < 2560) {
        int jj = j - 1280;
        g_w2T[jj * NH + o] = w2[(size_t)o * 1280 + jj];
    } else if (j < 2816) {
        int jj = j - 2560;
        g_pwT[jj * NH + o] = pw[(size_t)o * NH + jj];
    } else {
        int b = j - 2816;
        g_cmel[b * NW + o] = 0;
    }
}

// ---------------- parallel mel histogram ----------------
__global__ void mel_hist(const int* __restrict__ mel2w)
{
    int b = blockIdx.y;
    int t = blockIdx.x * 256 + threadIdx.x;
    int w = mel2w[(size_t)b * NM + t] - 1;
    atomicAdd(&g_cmel[b * NW + w], 1);
}

// ---------------- conv5 + channel-LN + relu: f32x2 pairs (t, t+8), TT=16, 2-deep prefetch ----------------
__global__ void __launch_bounds__(256, 2) conv_ln_relu(
                             const float* __restrict__ in,
                             const float* __restrict__ mask,
                             const float* __restrict__ wT,    // [(i*5+k)*NH + o], padded
                             const float* __restrict__ bias,
                             const float* __restrict__ lng,
                             const float* __restrict__ lnb,
                             float* __restrict__ out)
{
    const int TT = 16;
    __shared__ ull spu[12 * NH];              // 24 KB; pair rows
    __shared__ float mu_s[TT], rs_s[TT];

    int b  = blockIdx.x / (NT / TT);
    int t0 = (blockIdx.x % (NT / TT)) * TT;
    int o  = threadIdx.x;

    float* spf = (float*)spu;
    for (int idx = o; idx < 20 * NH; idx += 256) {
        int v = idx >> 8; int i = idx & 255;    // v -> x[t0+v-2]
        int t = t0 + v - 2;
        float val = 0.0f;
        if (t >= 0 && t < NT) val = in[((size_t)b * NT + t) * NH + i] * mask[b * NT + t];
        if (v < 12)  spf[(v * NH + i) * 2]           = val;
        if (v >= 8)  spf[((v - 8) * NH + i) * 2 + 1] = val;
    }
    __syncthreads();

    ull acc2[8];
    {
        float bo = bias[o];
        ull bp = pk2(bo, bo);
        #pragma unroll
        for (int j = 0; j < 8; j++) acc2[j] = bp;
    }

    // 2-deep software-pipelined weight loads (pad rows keep last prefetches in-bounds)
    const float* wp = wT + o;
    float a0 = wp[0], a1 = wp[NH], a2 = wp[2*NH], a3 = wp[3*NH], a4 = wp[4*NH];   // i
    wp += 5 * NH;
    float q0 = wp[0], q1 = wp[NH], q2 = wp[2*NH], q3 = wp[3*NH], q4 = wp[4*NH];   // i+1
    #pragma unroll 2
    for (int i = 0; i < NH; i++) {
        wp += 5 * NH;
        float n0 = wp[0], n1 = wp[NH], n2 = wp[2*NH], n3 = wp[3*NH], n4 = wp[4*NH];  // i+2
        ull W0 = pk2(a0, a0), W1 = pk2(a1, a1), W2 = pk2(a2, a2), W3 = pk2(a3, a3), W4 = pk2(a4, a4);
        ull p0 = spu[i], p1 = spu[NH + i], p2 = spu[2 * NH + i], p3 = spu[3 * NH + i];
        #pragma unroll
        for (int j = 0; j < 8; j++) {
            ull p4 = spu[(j + 4) * NH + i];
            ull s;
            MUL2(s, p0, W0);
            FMA2(s, p1, W1, s);
            FMA2(s, p2, W2, s);
            FMA2(s, p3, W3, s);
            FMA2(s, p4, W4, s);
            ADD2(acc2[j], acc2[j], s);
            p0 = p1; p1 = p2; p2 = p3; p3 = p4;
        }
        a0 = q0; a1 = q1; a2 = q2; a3 = q3; a4 = q4;
        q0 = n0; q1 = n1; q2 = n2; q3 = n3; q4 = n4;
    }
    __syncthreads();

    float* ys = (float*)spu;
    #pragma unroll
    for (int j = 0; j < 8; j++) {
        float a, bb;
        unpk2(acc2[j], a, bb);
        ys[j * NH + o]       = a;
        ys[(j + 8) * NH + o] = bb;
    }
    __syncthreads();

    int warp = o >> 5, lane = o & 31;
    for (int t = warp; t < TT; t += 8) {
        float s = 0.0f;
        for (int c = lane; c < NH; c += 32) s += ys[t * NH + c];
        for (int off = 16; off; off >>= 1) s += __shfl_xor_sync(0xffffffffu, s, off);
        float mu = s * (1.0f / NH);
        float v = 0.0f;
        for (int c = lane; c < NH; c += 32) { float d = ys[t * NH + c] - mu; v = fmaf(d, d, v); }
        for (int off = 16; off; off >>= 1) v += __shfl_xor_sync(0xffffffffu, v, off);
        v *= (1.0f / NH);
        if (lane == 0) { mu_s[t] = mu; rs_s[t] = 1.0f / sqrtf(v + 1e-4f); }
    }
    __syncthreads();

    float go = lng[o], lb = lnb[o];
    #pragma unroll
    for (int t = 0; t < TT; t++) {
        float y = (ys[t * NH + o] - mu_s[t]) * rs_s[t] * go + lb;
        out[((size_t)b * NT + t0 + t) * NH + o] = fmaxf(y, 0.0f);
    }
}

// ---------------- proj 1x1 + residual + gauss ch0 -> m0 (R3/R9 exact) ----------------
__global__ void __launch_bounds__(256) proj_gauss(
                           const float* __restrict__ x,
                           const float* __restrict__ mask,
                           const float* __restrict__ pb,
                           const float* __restrict__ gw,
                           const float* __restrict__ gb)
{
    const int TT = 16;
    __shared__ float hs[TT][NH];
    __shared__ float red2[256][TT + 1];

    int b  = blockIdx.x / (NT / TT);
    int t0 = (blockIdx.x % (NT / TT)) * TT;
    int o  = threadIdx.x;

    for (int idx = o; idx < TT * NH; idx += 256) {
        int tt = idx >> 8; int i = idx & 255;
        hs[tt][i] = g_h2[((size_t)b * NT + t0 + tt) * NH + i];
    }
    __syncthreads();

    float acc[TT];
    float pbo = pb[o];
    #pragma unroll
    for (int t = 0; t < TT; t++) acc[t] = pbo;

    const float* pwp = g_pwT + o;
    for (int i = 0; i < NH; i++) {
        float w = pwp[i * NH];
        #pragma unroll
        for (int t = 0; t < TT; t++) acc[t] = fmaf(w, hs[t][i], acc[t]);
    }

    float gwo = gw[o];
    #pragma unroll
    for (int t = 0; t < TT; t++) {
        float mt = mask[b * NT + t0 + t];
        float v = (x[((size_t)b * NT + t0 + t) * NH + o] + acc[t]) * mt;
        red2[o][t] = gwo * v;
    }
    __syncthreads();

    #pragma unroll
    for (int s = 128; s > 0; s >>= 1) {
        if (o < s) {
            #pragma unroll
            for (int t = 0; t < TT; t++) red2[o][t] += red2[o + s][t];
        }
        __syncthreads();
    }
    if (o < TT) {
        float g0 = red2[0][o] + gb[0];
        float mt = mask[b * NT + t0 + o];
        g_m0[b * NT + t0 + o] = (fmaxf(g0, 0.0f) + 1.0f) * mt;
    }
}

// ---------------- word stats, rescale, cumsum -> center ----------------
__global__ void stats_kernel(const int* __restrict__ x2w,
                             float* __restrict__ mword_out)
{
    int b = blockIdx.x;
    int tid = threadIdx.x;
    __shared__ int   cph[NW], sph[NW], smel[NW];
    __shared__ float sc[NW];
    __shared__ float mbuf[NT];

    if (tid < NW) cph[tid] = 0;
    __syncthreads();
    for (int p = tid; p < NT; p += 256) atomicAdd(&cph[x2w[b * NT + p] - 1], 1);
    __syncthreads();
    if (tid == 0) { int s = 0; for (int w = 0; w < NW; w++) { sph[w]  = s; s += cph[w]; } }
    if (tid == 1) { int s = 0; for (int w = 0; w < NW; w++) { smel[w] = s; s += g_cmel[b * NW + w]; } }
    __syncthreads();

    if (tid < NW) {
        int w = tid;
        int st = sph[w], c = cph[w];
        int cm = g_cmel[b * NW + w];
        float s = 0.0f;
        for (int j = 0; j < c; j++) s += g_m0[b * NT + st + j];
        mword_out[b * NW + w] = s;
        sc[w] = (float)cm / (s + 1e-4f);
        g_phs[b * NW + w] = st;      g_phc[b * NW + w] = c;
        g_mels[b * NW + w] = smel[w]; g_melc[b * NW + w] = cm;
    }
    __syncthreads();

    for (int p = tid; p < NT; p += 256) {
        int w = x2w[b * NT + p] - 1;
        float m0 = g_m0[b * NT + p];
        float d  = __fmul_rn(sc[w] - 1.0f, m0);
        mbuf[p]  = __fadd_rn(m0, d);
    }
    __syncthreads();

    if (tid == 0) {
        float c = 0.0f;
        for (int p = 0; p < NT; p++) {
            c = __fadd_rn(c, mbuf[p]);
            float half = __fmul_rn(0.5f, mbuf[p]);
            g_center[b * NT + p] = __fadd_rn(c, -half);
        }
    }
}

// ---------------- fused attention: missing-word blocks FIRST, then matched rows ----------------
#define MISS_BLKS (NW * NB * 4)     // 8192
__global__ void __launch_bounds__(256) attn_fused(
                             const float* __restrict__ x,
                             const int* __restrict__ mel2w,
                             float* __restrict__ outA,
                             float* __restrict__ outW)
{
    __shared__ float wsm[8][64];
    __shared__ float wts[8][NT];
    __shared__ float cen[NT];
    __shared__ float redA[8], redB[8];

    if (blockIdx.x < MISS_BLKS) {
        int idx = blockIdx.x;
        int w = idx & 255;
        int b = (idx >> 8) & 7;
        int z = idx >> 11;               // 0..3
        if (g_phc[b * NW + w] != 0) return;
        int mc = g_melc[b * NW + w];
        if (mc == 0) return;
        int ms = g_mels[b * NW + w];

        int tid = threadIdx.x;
        int lane = tid & 31, warp = tid >> 5;

        for (int p = tid; p < NT; p += 256) cen[p] = g_center[b * NT + p];
        __syncthreads();

        for (int r0 = z * 8; r0 < mc; r0 += 32) {
            int RT = min(8, mc - r0);
            for (int r = 0; r < RT; r++) {
                float tp = (float)(ms + r0 + r);
                float d0 = cen[tid] - tp;
                float lg0 = -(__fmul_rn(d0, d0)) / 10.0f;
                float m0v = __fadd_rn(lg0, -1e9f);
                float d1 = cen[tid + 256] - tp;
                float lg1 = -(__fmul_rn(d1, d1)) / 10.0f;
                float m1v = __fadd_rn(lg1, -1e9f);

                float mx = fmaxf(m0v, m1v);
                for (int off = 16; off; off >>= 1) mx = fmaxf(mx, __shfl_xor_sync(0xffffffffu, mx, off));
                if (lane == 0) redA[warp] = mx;
                __syncthreads();
                float mall = redA[0];
                #pragma unroll
                for (int k = 1; k < 8; k++) mall = fmaxf(mall, redA[k]);

                float e0 = expf(m0v - mall);
                float e1 = expf(m1v - mall);
                float ss = e0 + e1;
                for (int off = 16; off; off >>= 1) ss += __shfl_xor_sync(0xffffffffu, ss, off);
                if (lane == 0) redB[warp] = ss;
                __syncthreads();
                float tot = redB[0];
                #pragma unroll
                for (int k = 1; k < 8; k++) tot += redB[k];

                float w0 = e0 / tot, w1 = e1 / tot;
                wts[r][tid] = w0; wts[r][tid + 256] = w1;
                size_t wb = ((size_t)b * NM + ms + r0 + r) * NT;
                outW[wb + tid] = w0; outW[wb + tid + 256] = w1;
                __syncthreads();
            }
            __syncthreads();

            float a[8];
            #pragma unroll
            for (int r = 0; r < 8; r++) a[r] = 0.0f;
            for (int p = 0; p < NT; p++) {
                float xv = x[((size_t)b * NT + p) * NH + tid];
                #pragma unroll
                for (int r = 0; r < 8; r++) a[r] = fmaf(wts[r][p], xv, a[r]);
            }
            for (int r = 0; r < RT; r++)
                outA[((size_t)b * NM + ms + r0 + r) * NH + tid] = a[r];
            __syncthreads();
        }
    } else {
        int warp = threadIdx.x >> 5, lane = threadIdx.x & 31;
        int row = (blockIdx.x - MISS_BLKS) * 8 + warp;
        int b = row >> 12;
        int t = row & 4095;

        int w = mel2w[(size_t)b * NM + t] - 1;
        int cnt = g_phc[b * NW + w];
        if (cnt == 0) return;
        int lo = g_phs[b * NW + w];
        float tp = (float)t;

        float l0 = -3.4e38f, l1 = -3.4e38f;
        if (lane < cnt) {
            float d = g_center[b * NT + lo + lane] - tp;
            l0 = -(__fmul_rn(d, d)) / 10.0f;
        }
        if (lane + 32 < cnt) {
            float d = g_center[b * NT + lo + lane + 32] - tp;
            l1 = -(__fmul_rn(d, d)) / 10.0f;
        }
        float mx = fmaxf(l0, l1);
        for (int off = 16; off; off >>= 1) mx = fmaxf(mx, __shfl_xor_sync(0xffffffffu, mx, off));
        float e0 = (lane < cnt)      ? expf(l0 - mx) : 0.0f;
        float e1 = (lane + 32 < cnt) ? expf(l1 - mx) : 0.0f;
        float s = e0 + e1;
        for (int off = 16; off; off >>= 1) s += __shfl_xor_sync(0xffffffffu, s, off);
        wsm[warp][lane]      = e0 / s;
        wsm[warp][lane + 32] = e1 / s;
        __syncwarp();

        size_t wbase = ((size_t)b * NM + t) * NT;
        float4* w4 = (float4*)(outW + wbase);
        #pragma unroll
        for (int q = 0; q < 4; q++) {
            int p = q * 128 + lane * 4;
            int j0 = p - lo;
            float4 v;
            v.x = ((unsigned)(j0)     < (unsigned)cnt) ? wsm[warp][j0]     : 0.0f;
            v.y = ((unsigned)(j0 + 1) < (unsigned)cnt) ? wsm[warp][j0 + 1] : 0.0f;
            v.z = ((unsigned)(j0 + 2) < (unsigned)cnt) ? wsm[warp][j0 + 2] : 0.0f;
            v.w = ((unsigned)(j0 + 3) < (unsigned)cnt) ? wsm[warp][j0 + 3] : 0.0f;
            w4[q * 32 + lane] = v;
        }

        float4 a0 = make_float4(0.f, 0.f, 0.f, 0.f);
        float4 a1 = make_float4(0.f, 0.f, 0.f, 0.f);
        for (int j = 0; j < cnt; j++) {
            float wj = wsm[warp][j];
            const float4* xr = (const float4*)(x + ((size_t)b * NT + lo + j) * NH);
            float4 v0 = xr[lane * 2], v1 = xr[lane * 2 + 1];
            a0.x = fmaf(wj, v0.x, a0.x); a0.y = fmaf(wj, v0.y, a0.y);
            a0.z = fmaf(wj, v0.z, a0.z); a0.w = fmaf(wj, v0.w, a0.w);
            a1.x = fmaf(wj, v1.x, a1.x); a1.y = fmaf(wj, v1.y, a1.y);
            a1.z = fmaf(wj, v1.z, a1.z); a1.w = fmaf(wj, v1.w, a1.w);
        }
        float4* o4 = (float4*)(outA + ((size_t)b * NM + t) * NH);
        o4[lane * 2]     = a0;
        o4[lane * 2 + 1] = a1;
    }
}

// ---------------- launcher ----------------
extern "C" void kernel_launch(void* const* d_in, const int* in_sizes, int n_in,
                              void* d_out, int out_size)
{
    const float* x       = (const float*)d_in[0];
    const float* x_mask  = (const float*)d_in[1];
    const float* pre_w1  = (const float*)d_in[2];
    const float* pre_b1  = (const float*)d_in[3];
    const float* ln1_g   = (const float*)d_in[4];
    const float* ln1_b   = (const float*)d_in[5];
    const float* pre_w2  = (const float*)d_in[6];
    const float* pre_b2  = (const float*)d_in[7];
    const float* ln2_g   = (const float*)d_in[8];
    const float* ln2_b   = (const float*)d_in[9];
    const float* proj_w  = (const float*)d_in[10];
    const float* proj_b  = (const float*)d_in[11];
    const float* gauss_w = (const float*)d_in[12];
    const float* gauss_b = (const float*)d_in[13];
    const int*   x2word  = (const int*)d_in[14];
    const int*   mel2word= (const int*)d_in[15];

    float* outA  = (float*)d_out;
    float* outW  = outA + (size_t)NB * NM * NH;
    float* outMW = outW + (size_t)NB * NM * NT;

    float* h1;  cudaGetSymbolAddress((void**)&h1,  g_h1);
    float* h2;  cudaGetSymbolAddress((void**)&h2,  g_h2);
    float* w1T; cudaGetSymbolAddress((void**)&w1T, g_w1T);
    float* w2T; cudaGetSymbolAddress((void**)&w2T, g_w2T);

    transpose_weights<<<2824, 256>>>(pre_w1, pre_w2, proj_w);
    mel_hist<<<dim3(NM / 256, NB), 256>>>(mel2word);
    conv_ln_relu<<<NB * (NT / 16), 256>>>(x,  x_mask, w1T, pre_b1, ln1_g, ln1_b, h1);
    conv_ln_relu<<<NB * (NT / 16), 256>>>(h1, x_mask, w2T, pre_b2, ln2_g, ln2_b, h2);
    proj_gauss  <<<NB * (NT / 16), 256>>>(x, x_mask, proj_b, gauss_w, gauss_b);
    stats_kernel<<<NB, 256>>>(x2word, outMW);
    attn_fused  <<<MISS_BLKS + NB * NM / 8, 256>>>(x, mel2word, outA, outW);
}

// round 15
// speedup vs baseline: 1.0725x; 1.0494x over previous
#include <cuda_runtime.h>
#include <math.h>

#define NB 8
#define NT 512
#define NH 256
#define NM 4096
#define NW 256

typedef unsigned long long ull;

#define FMA2(d,a,b,c) asm("fma.rn.f32x2 %0,%1,%2,%3;" : "=l"(d) : "l"(a), "l"(b), "l"(c))
#define MUL2(d,a,b)   asm("mul.rn.f32x2 %0,%1,%2;"    : "=l"(d) : "l"(a), "l"(b))
#define ADD2(d,a,b)   asm("add.rn.f32x2 %0,%1,%2;"    : "=l"(d) : "l"(a), "l"(b))

__device__ __forceinline__ ull pk2(float a, float b) {
    ull d;
    asm("mov.b64 %0,{%1,%2};" : "=l"(d) : "r"(__float_as_uint(a)), "r"(__float_as_uint(b)));
    return d;
}
__device__ __forceinline__ void unpk2(ull v, float& a, float& b) {
    unsigned int l, h;
    asm("mov.b64 {%0,%1},%2;" : "=r"(l), "=r"(h) : "l"(v));
    a = __uint_as_float(l); b = __uint_as_float(h);
}

// ---------------- scratch ----------------
__device__ float g_h1[NB*NT*NH];
__device__ float g_h2[NB*NT*NH];
__device__ float g_m0[NB*NT];
__device__ float g_center[NB*NT];
__device__ int   g_phs[NB*NW];
__device__ int   g_phc[NB*NW];
__device__ int   g_mels[NB*NW];
__device__ int   g_melc[NB*NW];
__device__ int   g_cmel[NB*NW];
__device__ float g_w1T[NH*5*NH + 5*NH];   // [(i*5+k)*NH + o], +1 i-row pad for prefetch
__device__ float g_w2T[NH*5*NH + 5*NH];
__device__ float g_pwT[NH*NH];            // [i*NH + o]

// ---------------- weight transpose + cmel zero ----------------
__global__ void transpose_weights(const float* __restrict__ w1,
                                  const float* __restrict__ w2,
                                  const float* __restrict__ pw)
{
    int o = threadIdx.x;
    int j = blockIdx.x;
    if (j < 1280) {
        g_w1T[j * NH + o] = w1[(size_t)o * 1280 + j];
    } else if (j < 2560) {
        int jj = j - 1280;
        g_w2T[jj * NH + o] = w2[(size_t)o * 1280 + jj];
    } else if (j < 2816) {
        int jj = j - 2560;
        g_pwT[jj * NH + o] = pw[(size_t)o * NH + jj];
    } else {
        int b = j - 2816;
        g_cmel[b * NW + o] = 0;
    }
}

// ---------------- parallel mel histogram ----------------
__global__ void mel_hist(const int* __restrict__ mel2w)
{
    int b = blockIdx.y;
    int t = blockIdx.x * 256 + threadIdx.x;
    int w = mel2w[(size_t)b * NM + t] - 1;
    atomicAdd(&g_cmel[b * NW + w], 1);
}

// ---------------- conv5 + channel-LN + relu: R9 exact (f32x2 pairs (t,t+8), TT=16, 1-deep prefetch) ----------------
__global__ void __launch_bounds__(256, 2) conv_ln_relu(
                             const float* __restrict__ in,
                             const float* __restrict__ mask,
                             const float* __restrict__ wT,    // [(i*5+k)*NH + o], padded
                             const float* __restrict__ bias,
                             const float* __restrict__ lng,
                             const float* __restrict__ lnb,
                             float* __restrict__ out)
{
    const int TT = 16;
    __shared__ ull spu[12 * NH];              // 24 KB; pair rows
    __shared__ float mu_s[TT], rs_s[TT];

    int b  = blockIdx.x / (NT / TT);
    int t0 = (blockIdx.x % (NT / TT)) * TT;
    int o  = threadIdx.x;

    float* spf = (float*)spu;
    for (int idx = o; idx < 20 * NH; idx += 256) {
        int v = idx >> 8; int i = idx & 255;    // v -> x[t0+v-2]
        int t = t0 + v - 2;
        float val = 0.0f;
        if (t >= 0 && t < NT) val = in[((size_t)b * NT + t) * NH + i] * mask[b * NT + t];
        if (v < 12)  spf[(v * NH + i) * 2]           = val;
        if (v >= 8)  spf[((v - 8) * NH + i) * 2 + 1] = val;
    }
    __syncthreads();

    ull acc2[8];
    {
        float bo = bias[o];
        ull bp = pk2(bo, bo);
        #pragma unroll
        for (int j = 0; j < 8; j++) acc2[j] = bp;
    }

    // 1-deep software-pipelined weight loads (pad row keeps last prefetch in-bounds)
    const float* wp = wT + o;
    float c0 = wp[0], c1 = wp[NH], c2 = wp[2*NH], c3 = wp[3*NH], c4 = wp[4*NH];
    #pragma unroll 2
    for (int i = 0; i < NH; i++) {
        wp += 5 * NH;
        float n0 = wp[0], n1 = wp[NH], n2 = wp[2*NH], n3 = wp[3*NH], n4 = wp[4*NH];
        ull W0 = pk2(c0, c0), W1 = pk2(c1, c1), W2 = pk2(c2, c2), W3 = pk2(c3, c3), W4 = pk2(c4, c4);
        ull p0 = spu[i], p1 = spu[NH + i], p2 = spu[2 * NH + i], p3 = spu[3 * NH + i];
        #pragma unroll
        for (int j = 0; j < 8; j++) {
            ull p4 = spu[(j + 4) * NH + i];
            ull s;
            MUL2(s, p0, W0);
            FMA2(s, p1, W1, s);
            FMA2(s, p2, W2, s);
            FMA2(s, p3, W3, s);
            FMA2(s, p4, W4, s);
            ADD2(acc2[j], acc2[j], s);
            p0 = p1; p1 = p2; p2 = p3; p3 = p4;
        }
        c0 = n0; c1 = n1; c2 = n2; c3 = n3; c4 = n4;
    }
    __syncthreads();

    float* ys = (float*)spu;
    #pragma unroll
    for (int j = 0; j < 8; j++) {
        float a, bb;
        unpk2(acc2[j], a, bb);
        ys[j * NH + o]       = a;
        ys[(j + 8) * NH + o] = bb;
    }
    __syncthreads();

    int warp = o >> 5, lane = o & 31;
    for (int t = warp; t < TT; t += 8) {
        float s = 0.0f;
        for (int c = lane; c < NH; c += 32) s += ys[t * NH + c];
        for (int off = 16; off; off >>= 1) s += __shfl_xor_sync(0xffffffffu, s, off);
        float mu = s * (1.0f / NH);
        float v = 0.0f;
        for (int c = lane; c < NH; c += 32) { float d = ys[t * NH + c] - mu; v = fmaf(d, d, v); }
        for (int off = 16; off; off >>= 1) v += __shfl_xor_sync(0xffffffffu, v, off);
        v *= (1.0f / NH);
        if (lane == 0) { mu_s[t] = mu; rs_s[t] = 1.0f / sqrtf(v + 1e-4f); }
    }
    __syncthreads();

    float go = lng[o], lb = lnb[o];
    #pragma unroll
    for (int t = 0; t < TT; t++) {
        float y = (ys[t * NH + o] - mu_s[t]) * rs_s[t] * go + lb;
        out[((size_t)b * NT + t0 + t) * NH + o] = fmaxf(y, 0.0f);
    }
}

// ---------------- proj 1x1 + residual + gauss ch0 -> m0 ----------------
// 512 threads: thread (o, half) owns t in [half*8, half*8+8). Same per-(o,t) math
// and reduction order as the 256-thread version -> bit-identical m0.
__global__ void __launch_bounds__(512, 2) proj_gauss(
                           const float* __restrict__ x,
                           const float* __restrict__ mask,
                           const float* __restrict__ pb,
                           const float* __restrict__ gw,
                           const float* __restrict__ gb)
{
    const int TT = 16;
    __shared__ float hs[TT][NH];              // 16 KB
    __shared__ float red2[256][TT + 1];       // 17 KB

    int b  = blockIdx.x / (NT / TT);
    int t0 = (blockIdx.x % (NT / TT)) * TT;
    int tid  = threadIdx.x;
    int o    = tid & 255;
    int half = tid >> 8;                      // 0 or 1
    int tb   = half * 8;                      // this thread's t-base

    for (int idx = tid; idx < TT * NH; idx += 512) {
        int tt = idx >> 8; int i = idx & 255;
        hs[tt][i] = g_h2[((size_t)b * NT + t0 + tt) * NH + i];
    }
    __syncthreads();

    float acc[8];
    float pbo = pb[o];
    #pragma unroll
    for (int j = 0; j < 8; j++) acc[j] = pbo;

    const float* pwp = g_pwT + o;
    for (int i = 0; i < NH; i++) {
        float w = pwp[i * NH];
        #pragma unroll
        for (int j = 0; j < 8; j++) acc[j] = fmaf(w, hs[tb + j][i], acc[j]);
    }

    float gwo = gw[o];
    #pragma unroll
    for (int j = 0; j < 8; j++) {
        int t = tb + j;
        float mt = mask[b * NT + t0 + t];
        float v = (x[((size_t)b * NT + t0 + t) * NH + o] + acc[j]) * mt;
        red2[o][t] = gwo * v;
    }
    __syncthreads();

    // identical pairwise tree per (o,t); halves cover disjoint t-ranges
    #pragma unroll
    for (int s = 128; s > 0; s >>= 1) {
        if (o < s) {
            #pragma unroll
            for (int j = 0; j < 8; j++) red2[o][tb + j] += red2[o + s][tb + j];
        }
        __syncthreads();
    }
    if (tid < TT) {
        float g0 = red2[0][tid] + gb[0];
        float mt = mask[b * NT + t0 + tid];
        g_m0[b * NT + t0 + tid] = (fmaxf(g0, 0.0f) + 1.0f) * mt;
    }
}

// ---------------- word stats, rescale, cumsum -> center ----------------
__global__ void stats_kernel(const int* __restrict__ x2w,
                             float* __restrict__ mword_out)
{
    int b = blockIdx.x;
    int tid = threadIdx.x;
    __shared__ int   cph[NW], sph[NW], smel[NW];
    __shared__ float sc[NW];
    __shared__ float mbuf[NT];

    if (tid < NW) cph[tid] = 0;
    __syncthreads();
    for (int p = tid; p < NT; p += 256) atomicAdd(&cph[x2w[b * NT + p] - 1], 1);
    __syncthreads();
    if (tid == 0) { int s = 0; for (int w = 0; w < NW; w++) { sph[w]  = s; s += cph[w]; } }
    if (tid == 1) { int s = 0; for (int w = 0; w < NW; w++) { smel[w] = s; s += g_cmel[b * NW + w]; } }
    __syncthreads();

    if (tid < NW) {
        int w = tid;
        int st = sph[w], c = cph[w];
        int cm = g_cmel[b * NW + w];
        float s = 0.0f;
        for (int j = 0; j < c; j++) s += g_m0[b * NT + st + j];
        mword_out[b * NW + w] = s;
        sc[w] = (float)cm / (s + 1e-4f);
        g_phs[b * NW + w] = st;      g_phc[b * NW + w] = c;
        g_mels[b * NW + w] = smel[w]; g_melc[b * NW + w] = cm;
    }
    __syncthreads();

    for (int p = tid; p < NT; p += 256) {
        int w = x2w[b * NT + p] - 1;
        float m0 = g_m0[b * NT + p];
        float d  = __fmul_rn(sc[w] - 1.0f, m0);
        mbuf[p]  = __fadd_rn(m0, d);
    }
    __syncthreads();

    if (tid == 0) {
        float c = 0.0f;
        for (int p = 0; p < NT; p++) {
            c = __fadd_rn(c, mbuf[p]);
            float half = __fmul_rn(0.5f, mbuf[p]);
            g_center[b * NT + p] = __fadd_rn(c, -half);
        }
    }
}

// ---------------- fused attention: missing-word blocks FIRST, then matched rows ----------------
#define MISS_BLKS (NW * NB * 4)     // 8192
__global__ void __launch_bounds__(256) attn_fused(
                             const float* __restrict__ x,
                             const int* __restrict__ mel2w,
                             float* __restrict__ outA,
                             float* __restrict__ outW)
{
    __shared__ float wsm[8][64];
    __shared__ float wts[8][NT];
    __shared__ float cen[NT];
    __shared__ float redA[8], redB[8];

    if (blockIdx.x < MISS_BLKS) {
        int idx = blockIdx.x;
        int w = idx & 255;
        int b = (idx >> 8) & 7;
        int z = idx >> 11;               // 0..3
        if (g_phc[b * NW + w] != 0) return;
        int mc = g_melc[b * NW + w];
        if (mc == 0) return;
        int ms = g_mels[b * NW + w];

        int tid = threadIdx.x;
        int lane = tid & 31, warp = tid >> 5;

        for (int p = tid; p < NT; p += 256) cen[p] = g_center[b * NT + p];
        __syncthreads();

        for (int r0 = z * 8; r0 < mc; r0 += 32) {
            int RT = min(8, mc - r0);
            for (int r = 0; r < RT; r++) {
                float tp = (float)(ms + r0 + r);
                float d0 = cen[tid] - tp;
                float lg0 = -(__fmul_rn(d0, d0)) / 10.0f;
                float m0v = __fadd_rn(lg0, -1e9f);
                float d1 = cen[tid + 256] - tp;
                float lg1 = -(__fmul_rn(d1, d1)) / 10.0f;
                float m1v = __fadd_rn(lg1, -1e9f);

                float mx = fmaxf(m0v, m1v);
                for (int off = 16; off; off >>= 1) mx = fmaxf(mx, __shfl_xor_sync(0xffffffffu, mx, off));
                if (lane == 0) redA[warp] = mx;
                __syncthreads();
                float mall = redA[0];
                #pragma unroll
                for (int k = 1; k < 8; k++) mall = fmaxf(mall, redA[k]);

                float e0 = expf(m0v - mall);
                float e1 = expf(m1v - mall);
                float ss = e0 + e1;
                for (int off = 16; off; off >>= 1) ss += __shfl_xor_sync(0xffffffffu, ss, off);
                if (lane == 0) redB[warp] = ss;
                __syncthreads();
                float tot = redB[0];
                #pragma unroll
                for (int k = 1; k < 8; k++) tot += redB[k];

                float w0 = e0 / tot, w1 = e1 / tot;
                wts[r][tid] = w0; wts[r][tid + 256] = w1;
                size_t wb = ((size_t)b * NM + ms + r0 + r) * NT;
                outW[wb + tid] = w0; outW[wb + tid + 256] = w1;
                __syncthreads();
            }
            __syncthreads();

            float a[8];
            #pragma unroll
            for (int r = 0; r < 8; r++) a[r] = 0.0f;
            for (int p = 0; p < NT; p++) {
                float xv = x[((size_t)b * NT + p) * NH + tid];
                #pragma unroll
                for (int r = 0; r < 8; r++) a[r] = fmaf(wts[r][p], xv, a[r]);
            }
            for (int r = 0; r < RT; r++)
                outA[((size_t)b * NM + ms + r0 + r) * NH + tid] = a[r];
            __syncthreads();
        }
    } else {
        int warp = threadIdx.x >> 5, lane = threadIdx.x & 31;
        int row = (blockIdx.x - MISS_BLKS) * 8 + warp;
        int b = row >> 12;
        int t = row & 4095;

        int w = mel2w[(size_t)b * NM + t] - 1;
        int cnt = g_phc[b * NW + w];
        if (cnt == 0) return;
        int lo = g_phs[b * NW + w];
        float tp = (float)t;

        float l0 = -3.4e38f, l1 = -3.4e38f;
        if (lane < cnt) {
            float d = g_center[b * NT + lo + lane] - tp;
            l0 = -(__fmul_rn(d, d)) / 10.0f;
        }
        if (lane + 32 < cnt) {
            float d = g_center[b * NT + lo + lane + 32] - tp;
            l1 = -(__fmul_rn(d, d)) / 10.0f;
        }
        float mx = fmaxf(l0, l1);
        for (int off = 16; off; off >>= 1) mx = fmaxf(mx, __shfl_xor_sync(0xffffffffu, mx, off));
        float e0 = (lane < cnt)      ? expf(l0 - mx) : 0.0f;
        float e1 = (lane + 32 < cnt) ? expf(l1 - mx) : 0.0f;
        float s = e0 + e1;
        for (int off = 16; off; off >>= 1) s += __shfl_xor_sync(0xffffffffu, s, off);
        wsm[warp][lane]      = e0 / s;
        wsm[warp][lane + 32] = e1 / s;
        __syncwarp();

        size_t wbase = ((size_t)b * NM + t) * NT;
        float4* w4 = (float4*)(outW + wbase);
        #pragma unroll
        for (int q = 0; q < 4; q++) {
            int p = q * 128 + lane * 4;
            int j0 = p - lo;
            float4 v;
            v.x = ((unsigned)(j0)     < (unsigned)cnt) ? wsm[warp][j0]     : 0.0f;
            v.y = ((unsigned)(j0 + 1) < (unsigned)cnt) ? wsm[warp][j0 + 1] : 0.0f;
            v.z = ((unsigned)(j0 + 2) < (unsigned)cnt) ? wsm[warp][j0 + 2] : 0.0f;
            v.w = ((unsigned)(j0 + 3) < (unsigned)cnt) ? wsm[warp][j0 + 3] : 0.0f;
            w4[q * 32 + lane] = v;
        }

        float4 a0 = make_float4(0.f, 0.f, 0.f, 0.f);
        float4 a1 = make_float4(0.f, 0.f, 0.f, 0.f);
        for (int j = 0; j < cnt; j++) {
            float wj = wsm[warp][j];
            const float4* xr = (const float4*)(x + ((size_t)b * NT + lo + j) * NH);
            float4 v0 = xr[lane * 2], v1 = xr[lane * 2 + 1];
            a0.x = fmaf(wj, v0.x, a0.x); a0.y = fmaf(wj, v0.y, a0.y);
            a0.z = fmaf(wj, v0.z, a0.z); a0.w = fmaf(wj, v0.w, a0.w);
            a1.x = fmaf(wj, v1.x, a1.x); a1.y = fmaf(wj, v1.y, a1.y);
            a1.z = fmaf(wj, v1.z, a1.z); a1.w = fmaf(wj, v1.w, a1.w);
        }
        float4* o4 = (float4*)(outA + ((size_t)b * NM + t) * NH);
        o4[lane * 2]     = a0;
        o4[lane * 2 + 1] = a1;
    }
}

// ---------------- launcher ----------------
extern "C" void kernel_launch(void* const* d_in, const int* in_sizes, int n_in,
                              void* d_out, int out_size)
{
    const float* x       = (const float*)d_in[0];
    const float* x_mask  = (const float*)d_in[1];
    const float* pre_w1  = (const float*)d_in[2];
    const float* pre_b1  = (const float*)d_in[3];
    const float* ln1_g   = (const float*)d_in[4];
    const float* ln1_b   = (const float*)d_in[5];
    const float* pre_w2  = (const float*)d_in[6];
    const float* pre_b2  = (const float*)d_in[7];
    const float* ln2_g   = (const float*)d_in[8];
    const float* ln2_b   = (const float*)d_in[9];
    const float* proj_w  = (const float*)d_in[10];
    const float* proj_b  = (const float*)d_in[11];
    const float* gauss_w = (const float*)d_in[12];
    const float* gauss_b = (const float*)d_in[13];
    const int*   x2word  = (const int*)d_in[14];
    const int*   mel2word= (const int*)d_in[15];

    float* outA  = (float*)d_out;
    float* outW  = outA + (size_t)NB * NM * NH;
    float* outMW = outW + (size_t)NB * NM * NT;

    float* h1;  cudaGetSymbolAddress((void**)&h1,  g_h1);
    float* h2;  cudaGetSymbolAddress((void**)&h2,  g_h2);
    float* w1T; cudaGetSymbolAddress((void**)&w1T, g_w1T);
    float* w2T; cudaGetSymbolAddress((void**)&w2T, g_w2T);

    transpose_weights<<<2824, 256>>>(pre_w1, pre_w2, proj_w);
    mel_hist<<<dim3(NM / 256, NB), 256>>>(mel2word);
    conv_ln_relu<<<NB * (NT / 16), 256>>>(x,  x_mask, w1T, pre_b1, ln1_g, ln1_b, h1);
    conv_ln_relu<<<NB * (NT / 16), 256>>>(h1, x_mask, w2T, pre_b2, ln2_g, ln2_b, h2);
    proj_gauss  <<<NB * (NT / 16), 512>>>(x, x_mask, proj_b, gauss_w, gauss_b);
    stats_kernel<<<NB, 256>>>(x2word, outMW);
    attn_fused  <<<MISS_BLKS + NB * NM / 8, 256>>>(x, mel2word, outA, outW);
}